// round 2
// baseline (speedup 1.0000x reference)
#include <cuda_runtime.h>

// Problem constants (fixed by the reference setup; runtime sizes read from in_sizes)
#define DD   128
#define MAXN 50000
#define MAXR 8
#define K1   1152     // R*D + D
#define K2   256      // 2*D

// ---------- device scratch (allocation-free rule: __device__ globals) ----------
__device__ float g_Sx[(size_t)MAXN * K1];   // [N, R*D | x]  ~230 MB
__device__ float g_H [(size_t)MAXN * K2];   // [N, h1 | nbr] ~51 MB
__device__ float g_W1[K1 * DD];             // stacked relation weights + root
__device__ float g_W2[K2 * DD];             // [w_root^T ; w_rel^T]
__device__ int   g_cnt[MAXN * MAXR];        // per (dst, rel) edge counts
__device__ int   g_w64;                     // 1 if edge arrays are int64, 0 if int32

// ---------- index dtype detection (int64 vs int32), graph-capture safe ----------
// For int64 indices < 2^31 the odd 32-bit words are all 0; for int32 data they
// are random node indices (essentially never all zero across 1024 samples).
__global__ void k_detect(const int* __restrict__ ei32, int e) {
    __shared__ int nz;
    if (threadIdx.x == 0) nz = 0;
    __syncthreads();
    int words = 2 * e;   // lower bound on available 32-bit words for either dtype
    for (int i = threadIdx.x; i < 1024; i += blockDim.x) {
        int idx = 2 * i + 1;
        if (idx < words && ei32[idx] != 0) atomicAdd(&nz, 1);
    }
    __syncthreads();
    if (threadIdx.x == 0) g_w64 = (nz == 0) ? 1 : 0;
}

__device__ __forceinline__ long long getIdx(const void* __restrict__ p, size_t i, int w64) {
    if (w64) return ((const long long*)p)[i];
    return (long long)((const int*)p)[i];
}

// ---------- f32x2 packed FMA helpers ----------
__device__ __forceinline__ unsigned long long pack2(float a) {
    unsigned long long v;
    asm("mov.b64 %0, {%1, %1};" : "=l"(v) : "f"(a));
    return v;
}
__device__ __forceinline__ void fma2(unsigned long long& d, unsigned long long a,
                                     unsigned long long b) {
    asm("fma.rn.f32x2 %0, %1, %2, %3;" : "=l"(d) : "l"(a), "l"(b), "l"(d));
}
__device__ __forceinline__ float2 unpack2(unsigned long long v) {
    float2 r;
    asm("mov.b64 {%0, %1}, %2;" : "=f"(r.x), "=f"(r.y) : "l"(v));
    return r;
}

// ---------- zero kernels ----------
__global__ void k_zero_Sx(int n4) {
    int i = blockIdx.x * blockDim.x + threadIdx.x;
    if (i < n4) ((float4*)g_Sx)[i] = make_float4(0.f, 0.f, 0.f, 0.f);
}
__global__ void k_zero_H(int n4) {
    int i = blockIdx.x * blockDim.x + threadIdx.x;
    if (i < n4) ((float4*)g_H)[i] = make_float4(0.f, 0.f, 0.f, 0.f);
}
__global__ void k_zero_cnt(int n4) {
    int i = blockIdx.x * blockDim.x + threadIdx.x;
    if (i < n4) ((int4*)g_cnt)[i] = make_int4(0, 0, 0, 0);
}

// ---------- fold comp into basis; build stacked weights ----------
// W1[r*D+i][o] = sum_b comp[r,b]*basis[b,i,o];  W1[1024+i][o] = root[i][o]
// W2[i][o] = w_root[o][i];  W2[128+i][o] = w_rel[o][i]
__global__ void k_weights(const float* __restrict__ basis, const float* __restrict__ comp,
                          const float* __restrict__ root, const float* __restrict__ w_rel,
                          const float* __restrict__ w_root, int B_) {
    int idx = blockIdx.x * blockDim.x + threadIdx.x;
    const int n1 = K1 * DD;
    if (idx < n1) {
        int row = idx / DD, o = idx % DD;
        if (row < MAXR * DD) {
            int r = row / DD, i = row % DD;
            float acc = 0.f;
            for (int b = 0; b < B_; b++)
                acc += comp[r * B_ + b] * basis[((size_t)b * DD + i) * DD + o];
            g_W1[idx] = acc;
        } else {
            int i = row - MAXR * DD;
            g_W1[idx] = root[i * DD + o];
        }
    } else if (idx < n1 + K2 * DD) {
        int j = idx - n1;
        int row = j / DD, o = j % DD;
        g_W2[j] = (row < DD) ? w_root[o * DD + row] : w_rel[o * DD + (row - DD)];
    }
}

// ---------- copy x into tail columns of Sx ----------
__global__ void k_copyx(const float* __restrict__ x, int n) {
    int i = blockIdx.x * blockDim.x + threadIdx.x;
    if (i < n * 32) {
        int nn = i >> 5, c = i & 31;
        ((float4*)g_Sx)[(size_t)nn * (K1 / 4) + (MAXR * DD / 4) + c] =
            ((const float4*)x)[(size_t)nn * 32 + c];
    }
}

// ---------- per (dst, relation) counts ----------
__global__ void k_count(const void* __restrict__ ei, const void* __restrict__ et,
                        int e, int r) {
    int i = blockIdx.x * blockDim.x + threadIdx.x;
    if (i >= e) return;
    int w64 = g_w64;
    long long dst = getIdx(ei, (size_t)e + i, w64);
    int t = (int)getIdx(et, i, w64);
    atomicAdd(&g_cnt[dst * r + t], 1);
}

// ---------- layer-1 scatter: Sx[dst, t*D:] += norm * x[src] (one warp/edge) ----------
__global__ void k_scatter1(const float* __restrict__ x, const void* __restrict__ ei,
                           const void* __restrict__ et, int e, int r) {
    int w = (blockIdx.x * blockDim.x + threadIdx.x) >> 5;
    int lane = threadIdx.x & 31;
    if (w >= e) return;
    int w64 = g_w64;
    long long src = getIdx(ei, w, w64);
    long long dst = getIdx(ei, (size_t)e + w, w64);
    int t = (int)getIdx(et, w, w64);
    int c = g_cnt[dst * r + t];
    float norm = 1.0f / (float)(c > 0 ? c : 1);
    float4 v = ((const float4*)x)[src * 32 + lane];
    float* p = &g_Sx[dst * K1 + t * DD + lane * 4];
    asm volatile("red.global.add.v4.f32 [%0], {%1,%2,%3,%4};" ::"l"(p), "f"(v.x * norm),
                 "f"(v.y * norm), "f"(v.z * norm), "f"(v.w * norm)
                 : "memory");
}

// ---------- layer-2 scatter: H[dst, 128:] += h1[src] ----------
__global__ void k_scatter2(const void* __restrict__ ei, int e) {
    int w = (blockIdx.x * blockDim.x + threadIdx.x) >> 5;
    int lane = threadIdx.x & 31;
    if (w >= e) return;
    int w64 = g_w64;
    long long src = getIdx(ei, w, w64);
    long long dst = getIdx(ei, (size_t)e + w, w64);
    float4 v = ((const float4*)g_H)[src * 64 + lane];   // h1 half (cols 0..127)
    float* p = &g_H[dst * K2 + DD + lane * 4];
    asm volatile("red.global.add.v4.f32 [%0], {%1,%2,%3,%4};" ::"l"(p), "f"(v.x), "f"(v.y),
                 "f"(v.z), "f"(v.w)
                 : "memory");
}

// ---------- tiled fp32 GEMM with packed FFMA2 ----------
// MODE 1: h1 = Sx @ W1 + bias1 -> g_H[:, 0:128] (ldc=256)
// MODE 2: out = H @ W2 + b_rel -> Cext (ldc=128)
template <int KK, int MODE>
__global__ __launch_bounds__(256) void k_gemm(const float* __restrict__ bias,
                                              float* __restrict__ Cext, int M) {
    const float* A = (MODE == 1) ? g_Sx : g_H;
    const float* Bm = (MODE == 1) ? g_W1 : g_W2;
    float* C = (MODE == 1) ? g_H : Cext;
    const int ldc = (MODE == 1) ? K2 : DD;

    __shared__ float As[16][132];
    __shared__ float Bs[16][128];

    int tid = threadIdx.x;
    int tx = tid & 15, ty = tid >> 4;
    int m0 = blockIdx.x * 128;
    int aRow = tid >> 2, aCol = (tid & 3) * 4;
    int bRow = tid >> 5, bCol = (tid & 31) * 4;

    unsigned long long acc[8][4];
#pragma unroll
    for (int i = 0; i < 8; i++)
#pragma unroll
        for (int j = 0; j < 4; j++) acc[i][j] = 0ULL;

    for (int k0 = 0; k0 < KK; k0 += 16) {
#pragma unroll
        for (int i = 0; i < 2; i++) {
            int row = m0 + aRow + i * 64;
            float4 v = make_float4(0.f, 0.f, 0.f, 0.f);
            if (row < M) v = *(const float4*)&A[(size_t)row * KK + k0 + aCol];
            As[aCol + 0][aRow + i * 64] = v.x;
            As[aCol + 1][aRow + i * 64] = v.y;
            As[aCol + 2][aRow + i * 64] = v.z;
            As[aCol + 3][aRow + i * 64] = v.w;
        }
#pragma unroll
        for (int i = 0; i < 2; i++) {
            *(float4*)&Bs[bRow + i * 8][bCol] =
                *(const float4*)&Bm[(size_t)(k0 + bRow + i * 8) * DD + bCol];
        }
        __syncthreads();
#pragma unroll
        for (int k = 0; k < 16; k++) {
            float4 a0 = *(const float4*)&As[k][ty * 8];
            float4 a1 = *(const float4*)&As[k][ty * 8 + 4];
            const ulonglong2* bp = (const ulonglong2*)&Bs[k][tx * 8];
            ulonglong2 q0 = bp[0], q1 = bp[1];
            unsigned long long b0 = q0.x, b1 = q0.y, b2 = q1.x, b3 = q1.y;
            float a[8] = {a0.x, a0.y, a0.z, a0.w, a1.x, a1.y, a1.z, a1.w};
#pragma unroll
            for (int i = 0; i < 8; i++) {
                unsigned long long av = pack2(a[i]);
                fma2(acc[i][0], av, b0);
                fma2(acc[i][1], av, b1);
                fma2(acc[i][2], av, b2);
                fma2(acc[i][3], av, b3);
            }
        }
        __syncthreads();
    }

    float bv[8];
#pragma unroll
    for (int j = 0; j < 8; j++) bv[j] = bias[tx * 8 + j];
#pragma unroll
    for (int i = 0; i < 8; i++) {
        int row = m0 + ty * 8 + i;
        if (row < M) {
            float2 p0 = unpack2(acc[i][0]), p1 = unpack2(acc[i][1]);
            float2 p2 = unpack2(acc[i][2]), p3 = unpack2(acc[i][3]);
            float4 o0 = make_float4(p0.x + bv[0], p0.y + bv[1], p1.x + bv[2], p1.y + bv[3]);
            float4 o1 = make_float4(p2.x + bv[4], p2.y + bv[5], p3.x + bv[6], p3.y + bv[7]);
            *(float4*)&C[(size_t)row * ldc + tx * 8] = o0;
            *(float4*)&C[(size_t)row * ldc + tx * 8 + 4] = o1;
        }
    }
}

extern "C" void kernel_launch(void* const* d_in, const int* in_sizes, int n_in,
                              void* d_out, int out_size) {
    const float* x      = (const float*)d_in[0];
    const void*  ei     = d_in[1];
    const void*  et     = d_in[2];
    const float* basis  = (const float*)d_in[3];
    const float* comp   = (const float*)d_in[4];
    const float* root   = (const float*)d_in[5];
    const float* bias1  = (const float*)d_in[6];
    const float* w_rel  = (const float*)d_in[7];
    const float* b_rel  = (const float*)d_in[8];
    const float* w_root = (const float*)d_in[9];

    int n = in_sizes[0] / DD;
    int e = in_sizes[2];
    int b = in_sizes[3] / (DD * DD);
    int r = in_sizes[4] / b;   // 8

    // 0. detect index dtype (int64 vs int32)
    k_detect<<<1, 256>>>((const int*)ei, e);

    // 1. zero scratch
    {
        int n4 = n * (K1 / 4);
        k_zero_Sx<<<(n4 + 255) / 256, 256>>>(n4);
    }
    {
        int n4 = n * (K2 / 4);
        k_zero_H<<<(n4 + 255) / 256, 256>>>(n4);
    }
    {
        int n4 = (n * r + 3) / 4;
        k_zero_cnt<<<(n4 + 255) / 256, 256>>>(n4);
    }

    // 2. fold comp into basis, build stacked weights
    k_weights<<<((K1 + K2) * DD + 255) / 256, 256>>>(basis, comp, root, w_rel, w_root, b);

    // 3. copy x into tail columns of Sx
    k_copyx<<<(n * 32 + 255) / 256, 256>>>(x, n);

    // 4. per-(dst, rel) counts, then normalized scatter
    k_count<<<(e + 255) / 256, 256>>>(ei, et, e, r);
    k_scatter1<<<(e * 32 + 255) / 256, 256>>>(x, ei, et, e, r);

    // 5. h1 = [S | x] @ W1 + bias1  -> H[:, 0:128]
    k_gemm<K1, 1><<<(n + 127) / 128, 256>>>(bias1, nullptr, n);

    // 6. nbr scatter into H[:, 128:256]
    k_scatter2<<<(e * 32 + 255) / 256, 256>>>(ei, e);

    // 7. out = [h1 | nbr] @ [w_root^T ; w_rel^T] + b_rel
    k_gemm<K2, 2><<<(n + 127) / 128, 256>>>(b_rel, (float*)d_out, n);
}

// round 5
// speedup vs baseline: 2.0419x; 2.0419x over previous
#include <cuda_runtime.h>
#include <cuda_bf16.h>
#include <cstdint>

// Problem constants
#define DD    128
#define MAXN  50000
#define MAXR  8
#define K1S   384     // split-K layer1: [x_hi | x_lo | x_hi]
#define NOUT1 1152    // R*D + D (root)
#define K2S   768     // split-K layer2: [h_hi|nbr_hi | h_lo|nbr_lo | h_hi|nbr_hi]

// ---------------- device scratch ----------------
__device__ float          g_Y  [(size_t)MAXN * NOUT1];  // projected features (fp32)
__device__ __nv_bfloat16  g_A1 [(size_t)MAXN * K1S];    // split X
__device__ __nv_bfloat16  g_A2 [(size_t)MAXN * K2S];    // split [h1|nbr]
__device__ __nv_bfloat16  g_W1T[NOUT1 * K1S];           // B operand layer1 [Nout, K]
__device__ __nv_bfloat16  g_W2T[DD * K2S];              // B operand layer2
__device__ float          g_h1 [(size_t)MAXN * DD];
__device__ float          g_agg[(size_t)MAXN * DD];
__device__ float          g_nbr[(size_t)MAXN * DD];
__device__ int            g_cnt[MAXN * MAXR];
__device__ int            g_w64;

__device__ __forceinline__ uint32_t smem_u32(const void* p) {
    uint32_t a;
    asm("{ .reg .u64 t; cvta.to.shared.u64 t, %1; cvt.u32.u64 %0, t; }" : "=r"(a) : "l"(p));
    return a;
}

// ---------------- index dtype detection ----------------
__global__ void k_detect(const int* __restrict__ ei32, int e) {
    __shared__ int nz;
    if (threadIdx.x == 0) nz = 0;
    __syncthreads();
    int words = 2 * e;
    for (int i = threadIdx.x; i < 1024; i += blockDim.x) {
        int idx = 2 * i + 1;
        if (idx < words && ei32[idx] != 0) atomicAdd(&nz, 1);
    }
    __syncthreads();
    if (threadIdx.x == 0) g_w64 = (nz == 0) ? 1 : 0;
}
__device__ __forceinline__ long long getIdx(const void* __restrict__ p, size_t i, int w64) {
    if (w64) return ((const long long*)p)[i];
    return (long long)((const int*)p)[i];
}

// ---------------- zero agg/nbr/cnt ----------------
__global__ void k_zero(int n, int r) {
    int i = blockIdx.x * blockDim.x + threadIdx.x;
    int n4 = n * (DD / 4);
    if (i < n4) {
        ((float4*)g_agg)[i] = make_float4(0.f, 0.f, 0.f, 0.f);
        ((float4*)g_nbr)[i] = make_float4(0.f, 0.f, 0.f, 0.f);
    }
    if (i < (n * r + 3) / 4) ((int4*)g_cnt)[i] = make_int4(0, 0, 0, 0);
}

// ---------------- build split-bf16 weight operands ----------------
__global__ void k_weights(const float* __restrict__ basis, const float* __restrict__ comp,
                          const float* __restrict__ root, const float* __restrict__ w_rel,
                          const float* __restrict__ w_root, int B_) {
    int idx = blockIdx.x * blockDim.x + threadIdx.x;
    const int n1 = NOUT1 * DD;
    if (idx < n1) {
        int j = idx >> 7, c = idx & 127;   // j: output col of layer1, c: input feature
        float w;
        if (j < MAXR * DD) {
            int r = j >> 7, o = j & 127;
            w = 0.f;
            for (int b = 0; b < B_; b++)
                w += comp[r * B_ + b] * basis[((size_t)b * DD + c) * DD + o];
        } else {
            w = root[c * DD + (j - MAXR * DD)];
        }
        __nv_bfloat16 hi = __float2bfloat16(w);
        __nv_bfloat16 lo = __float2bfloat16(w - __bfloat162float(hi));
        g_W1T[j * K1S + c] = hi;
        g_W1T[j * K1S + 128 + c] = hi;
        g_W1T[j * K1S + 256 + c] = lo;
    } else if (idx < n1 + DD * 256) {
        int t = idx - n1;
        int o = t >> 8, c = t & 255;   // o: output col, c: [root inputs | rel inputs]
        float w = (c < DD) ? w_root[o * DD + c] : w_rel[o * DD + (c - DD)];
        __nv_bfloat16 hi = __float2bfloat16(w);
        __nv_bfloat16 lo = __float2bfloat16(w - __bfloat162float(hi));
        g_W2T[o * K2S + c] = hi;
        g_W2T[o * K2S + 256 + c] = hi;
        g_W2T[o * K2S + 512 + c] = lo;
    }
}

// ---------------- split X into A1 ----------------
__global__ void k_xsplit(const float* __restrict__ x, int n) {
    int i = blockIdx.x * blockDim.x + threadIdx.x;
    if (i >= n * DD) return;
    int nn = i >> 7, c = i & 127;
    float v = x[i];
    __nv_bfloat16 hi = __float2bfloat16(v);
    __nv_bfloat16 lo = __float2bfloat16(v - __bfloat162float(hi));
    size_t base = (size_t)nn * K1S;
    g_A1[base + c] = hi;
    g_A1[base + 128 + c] = lo;
    g_A1[base + 256 + c] = hi;
}

// ---------------- HMMA (mma.sync) bf16 GEMM ----------------
// C[m, n0:n0+128] = A[m, :KTOT] @ Bw[n, :KTOT]^T  (+ bias for MODE 2)
// MODE 1: g_A1 @ g_W1T -> g_Y (ldc 1152)
// MODE 2: g_A2 @ g_W2T -> Cext (ldc 128) + b_rel
// CTA: 128x128 tile, 8 warps in 4(m) x 2(n), warp tile 32x64.
template <int KTOT, int MODE>
__global__ __launch_bounds__(256) void k_gemm_mma(float* __restrict__ Cext,
                                                  const float* __restrict__ bias, int M) {
    const __nv_bfloat16* A  = (MODE == 1) ? g_A1 : g_A2;
    const __nv_bfloat16* Bw = (MODE == 1) ? g_W1T : g_W2T;
    float* C = (MODE == 1) ? g_Y : Cext;
    const int ldc = (MODE == 1) ? NOUT1 : DD;

    // 128 rows x 64 bf16 (128B) per tile, 16B-granule XOR swizzle
    __shared__ __nv_bfloat16 As[128 * 64];
    __shared__ __nv_bfloat16 Bs[128 * 64];

    int tid = threadIdx.x;
    int wid = tid >> 5, lane = tid & 31;
    int wm = wid & 3, wn = wid >> 2;
    int m0 = blockIdx.y * 128, n0 = blockIdx.x * 128;

    float acc[2][8][4];
#pragma unroll
    for (int i = 0; i < 2; i++)
#pragma unroll
        for (int j = 0; j < 8; j++)
#pragma unroll
            for (int q = 0; q < 4; q++) acc[i][j][q] = 0.f;

    uint32_t sA = smem_u32(As), sB = smem_u32(Bs);

    for (int kt = 0; kt < KTOT / 64; kt++) {
        // ---- load 128x64 A and B tiles (4 x uint4 per thread each) ----
#pragma unroll
        for (int i = 0; i < 4; i++) {
            int id = i * 256 + tid;
            int row = id >> 3, c8 = id & 7;
            uint32_t soff = row * 128 + ((c8 ^ (row & 7)) * 16);
            int ra = m0 + row;
            uint4 va = (ra < M) ? *(const uint4*)(A + (size_t)ra * KTOT + kt * 64 + c8 * 8)
                                : make_uint4(0u, 0u, 0u, 0u);
            *(uint4*)((char*)As + soff) = va;
            uint4 vb = *(const uint4*)(Bw + (size_t)(n0 + row) * KTOT + kt * 64 + c8 * 8);
            *(uint4*)((char*)Bs + soff) = vb;
        }
        __syncthreads();

#pragma unroll
        for (int k16 = 0; k16 < 4; k16++) {
            uint32_t a[2][4];
#pragma unroll
            for (int mi = 0; mi < 2; mi++) {
                int row = wm * 32 + mi * 16 + (lane & 15);
                int g = k16 * 2 + (lane >> 4);
                uint32_t addr = sA + row * 128 + ((g ^ (row & 7)) * 16);
                asm volatile("ldmatrix.sync.aligned.m8n8.x4.shared.b16 {%0,%1,%2,%3}, [%4];"
                             : "=r"(a[mi][0]), "=r"(a[mi][1]), "=r"(a[mi][2]), "=r"(a[mi][3])
                             : "r"(addr));
            }
            uint32_t b[8][2];
#pragma unroll
            for (int nq = 0; nq < 4; nq++) {
                int row = wn * 64 + nq * 16 + (lane & 15);
                int g = k16 * 2 + (lane >> 4);
                uint32_t addr = sB + row * 128 + ((g ^ (row & 7)) * 16);
                uint32_t r0, r1, r2, r3;
                asm volatile("ldmatrix.sync.aligned.m8n8.x4.shared.b16 {%0,%1,%2,%3}, [%4];"
                             : "=r"(r0), "=r"(r1), "=r"(r2), "=r"(r3)
                             : "r"(addr));
                b[nq * 2 + 0][0] = r0; b[nq * 2 + 0][1] = r2;
                b[nq * 2 + 1][0] = r1; b[nq * 2 + 1][1] = r3;
            }
#pragma unroll
            for (int mi = 0; mi < 2; mi++)
#pragma unroll
                for (int ni = 0; ni < 8; ni++)
                    asm volatile(
                        "mma.sync.aligned.m16n8k16.row.col.f32.bf16.bf16.f32 "
                        "{%0,%1,%2,%3}, {%4,%5,%6,%7}, {%8,%9}, {%0,%1,%2,%3};"
                        : "+f"(acc[mi][ni][0]), "+f"(acc[mi][ni][1]), "+f"(acc[mi][ni][2]),
                          "+f"(acc[mi][ni][3])
                        : "r"(a[mi][0]), "r"(a[mi][1]), "r"(a[mi][2]), "r"(a[mi][3]),
                          "r"(b[ni][0]), "r"(b[ni][1]));
        }
        __syncthreads();
    }

    // ---- epilogue ----
#pragma unroll
    for (int mi = 0; mi < 2; mi++) {
        int r0 = m0 + wm * 32 + mi * 16 + (lane >> 2);
#pragma unroll
        for (int ni = 0; ni < 8; ni++) {
            int col = n0 + wn * 64 + ni * 8 + (lane & 3) * 2;
            float b0 = 0.f, b1 = 0.f;
            if (MODE == 2) { b0 = bias[col]; b1 = bias[col + 1]; }
            if (r0 < M)
                *(float2*)(C + (size_t)r0 * ldc + col) =
                    make_float2(acc[mi][ni][0] + b0, acc[mi][ni][1] + b1);
            if (r0 + 8 < M)
                *(float2*)(C + (size_t)(r0 + 8) * ldc + col) =
                    make_float2(acc[mi][ni][2] + b0, acc[mi][ni][3] + b1);
        }
    }
}

// ---------------- per (dst, relation) counts ----------------
__global__ void k_count(const void* __restrict__ ei, const void* __restrict__ et, int e, int r) {
    int i = blockIdx.x * blockDim.x + threadIdx.x;
    if (i >= e) return;
    int w64 = g_w64;
    long long dst = getIdx(ei, (size_t)e + i, w64);
    int t = (int)getIdx(et, i, w64);
    atomicAdd(&g_cnt[dst * r + t], 1);
}

// ---------------- scatter1: agg[dst] += norm * Y[src, t*128:] ----------------
__global__ void k_scatter1(const void* __restrict__ ei, const void* __restrict__ et, int e,
                           int r) {
    int w = (blockIdx.x * blockDim.x + threadIdx.x) >> 5;
    int lane = threadIdx.x & 31;
    if (w >= e) return;
    int w64 = g_w64;
    long long src = getIdx(ei, w, w64);
    long long dst = getIdx(ei, (size_t)e + w, w64);
    int t = (int)getIdx(et, w, w64);
    int c = g_cnt[dst * r + t];
    float norm = 1.0f / (float)(c > 0 ? c : 1);
    float4 v = *(const float4*)&g_Y[(size_t)src * NOUT1 + t * DD + lane * 4];
    float* p = &g_agg[(size_t)dst * DD + lane * 4];
    asm volatile("red.global.add.v4.f32 [%0], {%1,%2,%3,%4};" ::"l"(p), "f"(v.x * norm),
                 "f"(v.y * norm), "f"(v.z * norm), "f"(v.w * norm)
                 : "memory");
}

// ---------------- compose h1 = agg + Y_root + bias1; fill A2 h1 slots ----------------
__global__ void k_compose(const float* __restrict__ bias1, int n) {
    int i = blockIdx.x * blockDim.x + threadIdx.x;
    if (i >= n * DD) return;
    int nn = i >> 7, c = i & 127;
    float h = g_agg[i] + g_Y[(size_t)nn * NOUT1 + MAXR * DD + c] + bias1[c];
    g_h1[i] = h;
    __nv_bfloat16 hi = __float2bfloat16(h);
    __nv_bfloat16 lo = __float2bfloat16(h - __bfloat162float(hi));
    size_t base = (size_t)nn * K2S;
    g_A2[base + c] = hi;          // block0: h1_hi
    g_A2[base + 256 + c] = lo;    // block2: h1_lo
    g_A2[base + 512 + c] = hi;    // block4: h1_hi
}

// ---------------- scatter2: nbr[dst] += h1[src] ----------------
__global__ void k_scatter2(const void* __restrict__ ei, int e) {
    int w = (blockIdx.x * blockDim.x + threadIdx.x) >> 5;
    int lane = threadIdx.x & 31;
    if (w >= e) return;
    int w64 = g_w64;
    long long src = getIdx(ei, w, w64);
    long long dst = getIdx(ei, (size_t)e + w, w64);
    float4 v = *(const float4*)&g_h1[(size_t)src * DD + lane * 4];
    float* p = &g_nbr[(size_t)dst * DD + lane * 4];
    asm volatile("red.global.add.v4.f32 [%0], {%1,%2,%3,%4};" ::"l"(p), "f"(v.x), "f"(v.y),
                 "f"(v.z), "f"(v.w)
                 : "memory");
}

// ---------------- fill A2 nbr slots ----------------
__global__ void k_nbrsplit(int n) {
    int i = blockIdx.x * blockDim.x + threadIdx.x;
    if (i >= n * DD) return;
    int nn = i >> 7, c = i & 127;
    float v = g_nbr[i];
    __nv_bfloat16 hi = __float2bfloat16(v);
    __nv_bfloat16 lo = __float2bfloat16(v - __bfloat162float(hi));
    size_t base = (size_t)nn * K2S;
    g_A2[base + 128 + c] = hi;    // block1: nbr_hi
    g_A2[base + 384 + c] = lo;    // block3: nbr_lo
    g_A2[base + 640 + c] = hi;    // block5: nbr_hi
}

extern "C" void kernel_launch(void* const* d_in, const int* in_sizes, int n_in,
                              void* d_out, int out_size) {
    const float* x      = (const float*)d_in[0];
    const void*  ei     = d_in[1];
    const void*  et     = d_in[2];
    const float* basis  = (const float*)d_in[3];
    const float* comp   = (const float*)d_in[4];
    const float* root   = (const float*)d_in[5];
    const float* bias1  = (const float*)d_in[6];
    const float* w_rel  = (const float*)d_in[7];
    const float* b_rel  = (const float*)d_in[8];
    const float* w_root = (const float*)d_in[9];

    int n = in_sizes[0] / DD;
    int e = in_sizes[2];
    int b = in_sizes[3] / (DD * DD);
    int r = in_sizes[4] / b;   // 8

    int mtiles = (n + 127) / 128;

    k_detect<<<1, 256>>>((const int*)ei, e);
    {
        int n4 = n * (DD / 4);
        k_zero<<<(n4 + 255) / 256, 256>>>(n, r);
    }
    k_weights<<<(NOUT1 * DD + DD * 256 + 255) / 256, 256>>>(basis, comp, root, w_rel, w_root, b);
    k_xsplit<<<(n * DD + 255) / 256, 256>>>(x, n);
    k_count<<<(e + 255) / 256, 256>>>(ei, et, e, r);

    // layer-1 projection: Y = [x_hi|x_lo|x_hi] @ W1T^T  (n-tile fastest -> A tile L2 reuse)
    k_gemm_mma<K1S, 1><<<dim3(NOUT1 / 128, mtiles), 256>>>(nullptr, nullptr, n);

    k_scatter1<<<((size_t)e * 32 + 255) / 256, 256>>>(ei, et, e, r);
    k_compose<<<(n * DD + 255) / 256, 256>>>(bias1, n);
    k_scatter2<<<((size_t)e * 32 + 255) / 256, 256>>>(ei, e);
    k_nbrsplit<<<(n * DD + 255) / 256, 256>>>(n);

    // layer-2: out = [h1|nbr] @ [w_root^T; w_rel^T] + b_rel
    k_gemm_mma<K2S, 2><<<dim3(1, mtiles), 256>>>((float*)d_out, b_rel, n);
}

// round 6
// speedup vs baseline: 2.4641x; 1.2068x over previous
#include <cuda_runtime.h>
#include <cuda_bf16.h>
#include <cstdint>

// Problem constants
#define DD    128
#define MAXN  50000
#define MAXR  8
#define KS    384     // split-K: [hi | lo | hi] blocks of 128
#define NOUT1 1152    // R*D + D (root)

// ---------------- device scratch ----------------
__device__ float          g_Y   [(size_t)MAXN * NOUT1];  // layer-1 projections (fp32)
__device__ __nv_bfloat16  g_A1  [(size_t)MAXN * KS];     // split X
__device__ __nv_bfloat16  g_A2  [(size_t)MAXN * KS];     // split h1
__device__ __nv_bfloat16  g_W1T [NOUT1 * KS];            // layer-1 B operand [Nout, K]
__device__ __nv_bfloat16  g_W2T [256 * KS];              // layer-2 B operand [root|rel]
__device__ float          g_agg [(size_t)MAXN * DD];
__device__ float          g_prel[(size_t)MAXN * DD];     // h1 @ w_rel^T
__device__ int            g_cnt [MAXN * MAXR];
__device__ int            g_w64;

__device__ __forceinline__ uint32_t smem_u32(const void* p) {
    uint32_t a;
    asm("{ .reg .u64 t; cvta.to.shared.u64 t, %1; cvt.u32.u64 %0, t; }" : "=r"(a) : "l"(p));
    return a;
}

// ---------------- index dtype detection ----------------
__global__ void k_detect(const int* __restrict__ ei32, int e) {
    __shared__ int nz;
    if (threadIdx.x == 0) nz = 0;
    __syncthreads();
    int words = 2 * e;
    for (int i = threadIdx.x; i < 1024; i += blockDim.x) {
        int idx = 2 * i + 1;
        if (idx < words && ei32[idx] != 0) atomicAdd(&nz, 1);
    }
    __syncthreads();
    if (threadIdx.x == 0) g_w64 = (nz == 0) ? 1 : 0;
}
__device__ __forceinline__ long long getIdx(const void* __restrict__ p, size_t i, int w64) {
    if (w64) return ((const long long*)p)[i];
    return (long long)((const int*)p)[i];
}

// ---------------- zero agg/cnt ----------------
__global__ void k_zero(int n, int r) {
    int i = blockIdx.x * blockDim.x + threadIdx.x;
    if (i < n * (DD / 4)) ((float4*)g_agg)[i] = make_float4(0.f, 0.f, 0.f, 0.f);
    if (i < (n * r + 3) / 4) ((int4*)g_cnt)[i] = make_int4(0, 0, 0, 0);
}

// ---------------- 8-wide split pack ----------------
union Pack8 {
    __nv_bfloat16 b[8];
    uint4 u;
};
__device__ __forceinline__ void split8(float4 a, float4 c, uint4& hi, uint4& lo) {
    float f[8] = {a.x, a.y, a.z, a.w, c.x, c.y, c.z, c.w};
    Pack8 H, L;
#pragma unroll
    for (int j = 0; j < 8; j++) {
        __nv_bfloat16 h = __float2bfloat16(f[j]);
        H.b[j] = h;
        L.b[j] = __float2bfloat16(f[j] - __bfloat162float(h));
    }
    hi = H.u;
    lo = L.u;
}

// ---------------- build split-bf16 weight operands ----------------
__global__ void k_weights(const float* __restrict__ basis, const float* __restrict__ comp,
                          const float* __restrict__ root, const float* __restrict__ w_rel,
                          const float* __restrict__ w_root, int B_) {
    int idx = blockIdx.x * blockDim.x + threadIdx.x;
    const int n1 = NOUT1 * DD;
    if (idx < n1) {
        int j = idx >> 7, c = idx & 127;   // j: layer-1 output col, c: input feature
        float w;
        if (j < MAXR * DD) {
            int r = j >> 7, o = j & 127;
            w = 0.f;
            for (int b = 0; b < B_; b++)
                w += comp[r * B_ + b] * basis[((size_t)b * DD + c) * DD + o];
        } else {
            w = root[c * DD + (j - MAXR * DD)];
        }
        __nv_bfloat16 hi = __float2bfloat16(w);
        __nv_bfloat16 lo = __float2bfloat16(w - __bfloat162float(hi));
        g_W1T[j * KS + c] = hi;
        g_W1T[j * KS + 128 + c] = hi;
        g_W1T[j * KS + 256 + c] = lo;
    } else if (idx < n1 + 256 * DD) {
        int t = idx - n1;
        int o = t >> 7, c = t & 127;   // o<128: w_root row o ; o>=128: w_rel row o-128
        float w = (o < DD) ? w_root[o * DD + c] : w_rel[(o - DD) * DD + c];
        __nv_bfloat16 hi = __float2bfloat16(w);
        __nv_bfloat16 lo = __float2bfloat16(w - __bfloat162float(hi));
        g_W2T[o * KS + c] = hi;
        g_W2T[o * KS + 128 + c] = hi;
        g_W2T[o * KS + 256 + c] = lo;
    }
}

// ---------------- split X into A1 (8 cols / thread) ----------------
__global__ void k_xsplit(const float* __restrict__ x, int n) {
    int i = blockIdx.x * blockDim.x + threadIdx.x;
    if (i >= n * 16) return;
    int nn = i >> 4, g = i & 15;
    const float4* src = (const float4*)(x + (size_t)nn * DD + g * 8);
    uint4 hi, lo;
    split8(src[0], src[1], hi, lo);
    __nv_bfloat16* base = g_A1 + (size_t)nn * KS + g * 8;
    *(uint4*)(base) = hi;
    *(uint4*)(base + 128) = lo;
    *(uint4*)(base + 256) = hi;
}

// ---------------- HMMA bf16 GEMM, cp.async double-buffered ----------------
// K = 384 for both layers. CTA 128x128, 8 warps 4(m)x2(n), warp tile 32x64.
// MODE 1: g_A1 @ g_W1T -> g_Y[m, n0:n0+128]            (ldc 1152, no bias)
// MODE 2: g_A2 @ g_W2T -> n0==0: d_out + b_rel (ldc 128)
//                         n0==128: g_prel     (ldc 128)
template <int MODE>
__global__ __launch_bounds__(256) void k_gemm_mma(float* __restrict__ Cext,
                                                  const float* __restrict__ bias, int M) {
    const __nv_bfloat16* A  = (MODE == 1) ? g_A1 : g_A2;
    const __nv_bfloat16* Bw = (MODE == 1) ? g_W1T : g_W2T;

    extern __shared__ char dsm[];
    uint32_t s0 = smem_u32(dsm);   // [As0 16K][Bs0 16K][As1 16K][Bs1 16K]

    int tid = threadIdx.x;
    int wid = tid >> 5, lane = tid & 31;
    int wm = wid & 3, wn = wid >> 2;
    int m0 = blockIdx.y * 128, n0 = blockIdx.x * 128;

    float acc[2][8][4];
#pragma unroll
    for (int i = 0; i < 2; i++)
#pragma unroll
        for (int j = 0; j < 8; j++)
#pragma unroll
            for (int q = 0; q < 4; q++) acc[i][j][q] = 0.f;

    // async tile load: one 16B cp.async per (A,B) per thread x4
    auto load_tile = [&](int kt, int buf) {
        uint32_t sa = s0 + buf * 32768, sb = sa + 16384;
#pragma unroll
        for (int i = 0; i < 4; i++) {
            int id = i * 256 + tid;
            int row = id >> 3, c8 = id & 7;
            uint32_t soff = row * 128 + ((c8 ^ (row & 7)) * 16);
            const void* gA = A + (size_t)(m0 + row) * KS + kt * 64 + c8 * 8;
            int szA = (m0 + row < M) ? 16 : 0;
            asm volatile("cp.async.ca.shared.global [%0], [%1], 16, %2;" ::"r"(sa + soff),
                         "l"(gA), "r"(szA)
                         : "memory");
            const void* gB = Bw + (size_t)(n0 + row) * KS + kt * 64 + c8 * 8;
            asm volatile("cp.async.ca.shared.global [%0], [%1], 16;" ::"r"(sb + soff), "l"(gB)
                         : "memory");
        }
        asm volatile("cp.async.commit_group;" ::: "memory");
    };

    const int NK = KS / 64;   // 6
    load_tile(0, 0);
    int buf = 0;
    for (int kt = 0; kt < NK; kt++) {
        if (kt + 1 < NK)
            load_tile(kt + 1, buf ^ 1);
        else
            asm volatile("cp.async.commit_group;" ::: "memory");   // keep group count uniform
        asm volatile("cp.async.wait_group 1;" ::: "memory");
        __syncthreads();

        uint32_t sA = s0 + buf * 32768, sB = sA + 16384;
#pragma unroll
        for (int k16 = 0; k16 < 4; k16++) {
            uint32_t a[2][4];
#pragma unroll
            for (int mi = 0; mi < 2; mi++) {
                int row = wm * 32 + mi * 16 + (lane & 15);
                int g = k16 * 2 + (lane >> 4);
                uint32_t addr = sA + row * 128 + ((g ^ (row & 7)) * 16);
                asm volatile("ldmatrix.sync.aligned.m8n8.x4.shared.b16 {%0,%1,%2,%3}, [%4];"
                             : "=r"(a[mi][0]), "=r"(a[mi][1]), "=r"(a[mi][2]), "=r"(a[mi][3])
                             : "r"(addr));
            }
            uint32_t b[8][2];
#pragma unroll
            for (int nq = 0; nq < 4; nq++) {
                int row = wn * 64 + nq * 16 + (lane & 15);
                int g = k16 * 2 + (lane >> 4);
                uint32_t addr = sB + row * 128 + ((g ^ (row & 7)) * 16);
                uint32_t r0, r1, r2, r3;
                asm volatile("ldmatrix.sync.aligned.m8n8.x4.shared.b16 {%0,%1,%2,%3}, [%4];"
                             : "=r"(r0), "=r"(r1), "=r"(r2), "=r"(r3)
                             : "r"(addr));
                b[nq * 2 + 0][0] = r0; b[nq * 2 + 0][1] = r2;
                b[nq * 2 + 1][0] = r1; b[nq * 2 + 1][1] = r3;
            }
#pragma unroll
            for (int mi = 0; mi < 2; mi++)
#pragma unroll
                for (int ni = 0; ni < 8; ni++)
                    asm volatile(
                        "mma.sync.aligned.m16n8k16.row.col.f32.bf16.bf16.f32 "
                        "{%0,%1,%2,%3}, {%4,%5,%6,%7}, {%8,%9}, {%0,%1,%2,%3};"
                        : "+f"(acc[mi][ni][0]), "+f"(acc[mi][ni][1]), "+f"(acc[mi][ni][2]),
                          "+f"(acc[mi][ni][3])
                        : "r"(a[mi][0]), "r"(a[mi][1]), "r"(a[mi][2]), "r"(a[mi][3]),
                          "r"(b[ni][0]), "r"(b[ni][1]));
        }
        __syncthreads();
        buf ^= 1;
    }

    // ---- epilogue ----
    float* C;
    int ldc, cbase;
    const float* bptr = nullptr;
    if (MODE == 1) {
        C = g_Y; ldc = NOUT1; cbase = n0;
    } else {
        ldc = DD; cbase = 0;
        if (n0 == 0) { C = Cext; bptr = bias; }
        else         { C = g_prel; }
    }
#pragma unroll
    for (int mi = 0; mi < 2; mi++) {
        int r0 = m0 + wm * 32 + mi * 16 + (lane >> 2);
#pragma unroll
        for (int ni = 0; ni < 8; ni++) {
            int ct = wn * 64 + ni * 8 + (lane & 3) * 2;
            float b0 = 0.f, b1 = 0.f;
            if (MODE == 2 && bptr) { b0 = bptr[ct]; b1 = bptr[ct + 1]; }
            if (r0 < M)
                *(float2*)(C + (size_t)r0 * ldc + cbase + ct) =
                    make_float2(acc[mi][ni][0] + b0, acc[mi][ni][1] + b1);
            if (r0 + 8 < M)
                *(float2*)(C + (size_t)(r0 + 8) * ldc + cbase + ct) =
                    make_float2(acc[mi][ni][2] + b0, acc[mi][ni][3] + b1);
        }
    }
}

// ---------------- per (dst, relation) counts ----------------
__global__ void k_count(const void* __restrict__ ei, const void* __restrict__ et, int e, int r) {
    int i = blockIdx.x * blockDim.x + threadIdx.x;
    if (i >= e) return;
    int w64 = g_w64;
    long long dst = getIdx(ei, (size_t)e + i, w64);
    int t = (int)getIdx(et, i, w64);
    atomicAdd(&g_cnt[dst * r + t], 1);
}

// ---------------- scatter1: agg[dst] += norm * Y[src, t*128:] ----------------
__global__ void k_scatter1(const void* __restrict__ ei, const void* __restrict__ et, int e,
                           int r) {
    int w = (blockIdx.x * blockDim.x + threadIdx.x) >> 5;
    int lane = threadIdx.x & 31;
    if (w >= e) return;
    int w64 = g_w64;
    long long src = getIdx(ei, w, w64);
    long long dst = getIdx(ei, (size_t)e + w, w64);
    int t = (int)getIdx(et, w, w64);
    int c = g_cnt[dst * r + t];
    float norm = 1.0f / (float)(c > 0 ? c : 1);
    float4 v = *(const float4*)&g_Y[(size_t)src * NOUT1 + t * DD + lane * 4];
    float* p = &g_agg[(size_t)dst * DD + lane * 4];
    asm volatile("red.global.add.v4.f32 [%0], {%1,%2,%3,%4};" ::"l"(p), "f"(v.x * norm),
                 "f"(v.y * norm), "f"(v.z * norm), "f"(v.w * norm)
                 : "memory");
}

// ---------------- compose h1 = agg + Y_root + bias1 -> split into A2 ----------------
__global__ void k_compose(const float* __restrict__ bias1, int n) {
    int i = blockIdx.x * blockDim.x + threadIdx.x;
    if (i >= n * 16) return;
    int nn = i >> 4, g = i & 15;
    const float4* pa = (const float4*)(g_agg + (size_t)nn * DD + g * 8);
    const float4* py = (const float4*)(g_Y + (size_t)nn * NOUT1 + MAXR * DD + g * 8);
    const float4* pb = (const float4*)(bias1 + g * 8);
    float4 a0 = pa[0], a1 = pa[1], y0 = py[0], y1 = py[1], b0 = pb[0], b1 = pb[1];
    float4 h0 = make_float4(a0.x + y0.x + b0.x, a0.y + y0.y + b0.y, a0.z + y0.z + b0.z,
                            a0.w + y0.w + b0.w);
    float4 h1 = make_float4(a1.x + y1.x + b1.x, a1.y + y1.y + b1.y, a1.z + y1.z + b1.z,
                            a1.w + y1.w + b1.w);
    uint4 hi, lo;
    split8(h0, h1, hi, lo);
    __nv_bfloat16* base = g_A2 + (size_t)nn * KS + g * 8;
    *(uint4*)(base) = hi;
    *(uint4*)(base + 128) = lo;
    *(uint4*)(base + 256) = hi;
}

// ---------------- scatter2: out[dst] += p_rel[src] ----------------
__global__ void k_scatter2(const void* __restrict__ ei, float* __restrict__ out, int e) {
    int w = (blockIdx.x * blockDim.x + threadIdx.x) >> 5;
    int lane = threadIdx.x & 31;
    if (w >= e) return;
    int w64 = g_w64;
    long long src = getIdx(ei, w, w64);
    long long dst = getIdx(ei, (size_t)e + w, w64);
    float4 v = *(const float4*)&g_prel[(size_t)src * DD + lane * 4];
    float* p = out + (size_t)dst * DD + lane * 4;
    asm volatile("red.global.add.v4.f32 [%0], {%1,%2,%3,%4};" ::"l"(p), "f"(v.x), "f"(v.y),
                 "f"(v.z), "f"(v.w)
                 : "memory");
}

extern "C" void kernel_launch(void* const* d_in, const int* in_sizes, int n_in,
                              void* d_out, int out_size) {
    const float* x      = (const float*)d_in[0];
    const void*  ei     = d_in[1];
    const void*  et     = d_in[2];
    const float* basis  = (const float*)d_in[3];
    const float* comp   = (const float*)d_in[4];
    const float* root   = (const float*)d_in[5];
    const float* bias1  = (const float*)d_in[6];
    const float* w_rel  = (const float*)d_in[7];
    const float* b_rel  = (const float*)d_in[8];
    const float* w_root = (const float*)d_in[9];

    int n = in_sizes[0] / DD;
    int e = in_sizes[2];
    int b = in_sizes[3] / (DD * DD);
    int r = in_sizes[4] / b;   // 8

    int mtiles = (n + 127) / 128;
    const int SMEM = 65536;
    cudaFuncSetAttribute(k_gemm_mma<1>, cudaFuncAttributeMaxDynamicSharedMemorySize, SMEM);
    cudaFuncSetAttribute(k_gemm_mma<2>, cudaFuncAttributeMaxDynamicSharedMemorySize, SMEM);

    k_detect<<<1, 256>>>((const int*)ei, e);
    {
        int n4 = n * (DD / 4);
        k_zero<<<(n4 + 255) / 256, 256>>>(n, r);
    }
    k_weights<<<((NOUT1 + 256) * DD + 255) / 256, 256>>>(basis, comp, root, w_rel, w_root, b);
    k_xsplit<<<(n * 16 + 255) / 256, 256>>>(x, n);
    k_count<<<(e + 255) / 256, 256>>>(ei, et, e, r);

    // layer-1 projection: Y = [x_hi|x_lo|x_hi] @ W1T^T
    k_gemm_mma<1><<<dim3(NOUT1 / 128, mtiles), 256, SMEM>>>(nullptr, nullptr, n);

    k_scatter1<<<((size_t)e * 32 + 255) / 256, 256>>>(ei, et, e, r);
    k_compose<<<(n * 16 + 255) / 256, 256>>>(bias1, n);

    // layer-2: n0=0 -> d_out = h1@w_root^T + b_rel ; n0=128 -> g_prel = h1@w_rel^T
    k_gemm_mma<2><<<dim3(2, mtiles), 256, SMEM>>>((float*)d_out, b_rel, n);

    k_scatter2<<<((size_t)e * 32 + 255) / 256, 256>>>(ei, (float*)d_out, e);
}